// round 5
// baseline (speedup 1.0000x reference)
#include <cuda_runtime.h>
#include <cuda_bf16.h>
#include <math.h>

// Problem constants (fixed by the dataset)
#define NN 8192      // nodes
#define EE 24576     // edges
#define DD 4         // node feature dim
#define HH 100       // hidden units

// ---------------------------------------------------------------------------
// Device scratch (no allocations allowed in kernel_launch)
// ---------------------------------------------------------------------------
__device__ int   g_idx_i[EE];
__device__ int   g_idx_o[EE];
__device__ float g_mi[NN * DD];
__device__ float g_mo[NN * DD];

// ---------------------------------------------------------------------------
// Kernel 1: recover idx_i / idx_o from the dense one-hot incidence matrices,
// plus accumulator zeroing in the first blocks.
//
// Each column of Ri/Ro [N, E] (row-major) has exactly one 1.0; over a row
// chunk compute fidx = sum_r r*M[r,c], found = sum_r M[r,c]; the unique
// chunk that contains the 1.0 writes idx = fidx (no atomics).
// This kernel is the HBM roofline: 2 * N * E * 4B = 1.61 GB streamed once.
//
// R5: persistent grid-stride over fine work units. Exactly 4 blocks/SM x 148
// SMs = 592 blocks = ONE wave (no wave-transition stragglers). Work unit =
// 1024 cols x 64 rows of one matrix -> 6144 units, ~10.4 units/block, so the
// finish-time imbalance is <=1 unit (~10%) instead of a whole tail wave.
// ---------------------------------------------------------------------------
#define SCAN_THREADS     256
#define SCAN_BLOCKS      592                     // 4 per SM x 148 SMs
#define COLS_PER_UNIT    (SCAN_THREADS * 4)      // 1024
#define COL_UNITS        (EE / COLS_PER_UNIT)    // 24
#define ROWS_PER_UNIT    64
#define ROW_UNITS        (NN / ROWS_PER_UNIT)    // 128
#define UNITS_PER_MAT    (COL_UNITS * ROW_UNITS) // 3072
#define TOTAL_UNITS      (2 * UNITS_PER_MAT)     // 6144
#define BATCH            8

__global__ __launch_bounds__(SCAN_THREADS, 4)
void find_idx_kernel(const float* __restrict__ Ri, const float* __restrict__ Ro) {
    // --- prologue: zero g_mi / g_mo (ready before scatter_kernel via
    //     kernel-boundary ordering). 128 blocks x 256 threads = 32768 = NN*DD.
    if (blockIdx.x < 128) {
        int t = blockIdx.x * SCAN_THREADS + threadIdx.x;
        g_mi[t] = 0.0f;
        g_mo[t] = 0.0f;
    }

    const int row_stride4 = EE / 4;  // float4 elements per row

    for (int u = blockIdx.x; u < TOTAL_UNITS; u += SCAN_BLOCKS) {
        const int mat   = u / UNITS_PER_MAT;       // 0 -> Ri, 1 -> Ro
        const int rem   = u - mat * UNITS_PER_MAT;
        const int chunk = rem / COL_UNITS;         // row chunk
        const int colb  = rem - chunk * COL_UNITS; // column block

        const float* M   = (mat == 0) ? Ri : Ro;
        int*         out = (mat == 0) ? g_idx_i : g_idx_o;

        const int col = colb * COLS_PER_UNIT + threadIdx.x * 4;
        const int r0  = chunk * ROWS_PER_UNIT;

        const float4* p = reinterpret_cast<const float4*>(M + (long)r0 * EE + col);

        float fi0 = 0.f, fi1 = 0.f, fi2 = 0.f, fi3 = 0.f;
        float ff0 = 0.f, ff1 = 0.f, ff2 = 0.f, ff3 = 0.f;

        #pragma unroll
        for (int rb = 0; rb < ROWS_PER_UNIT; rb += BATCH) {
            // front-batch BATCH independent LDG.128s (deep MLP)
            float4 v[BATCH];
            #pragma unroll
            for (int j = 0; j < BATCH; ++j)
                v[j] = __ldcs(p + (long)(rb + j) * row_stride4);  // streaming

            #pragma unroll
            for (int j = 0; j < BATCH; ++j) {
                float fr = (float)(r0 + rb + j);
                fi0 = fmaf(v[j].x, fr, fi0); ff0 += v[j].x;
                fi1 = fmaf(v[j].y, fr, fi1); ff1 += v[j].y;
                fi2 = fmaf(v[j].z, fr, fi2); ff2 += v[j].z;
                fi3 = fmaf(v[j].w, fr, fi3); ff3 += v[j].w;
            }
        }

        if (ff0 != 0.f) out[col + 0] = (int)fi0;
        if (ff1 != 0.f) out[col + 1] = (int)fi1;
        if (ff2 != 0.f) out[col + 2] = (int)fi2;
        if (ff3 != 0.f) out[col + 3] = (int)fi3;
    }
}

// ---------------------------------------------------------------------------
// Kernel 2: per-edge weighted scatter
//   mi[idx_i[k]] += e[k] * X[idx_o[k]]
//   mo[idx_o[k]] += e[k] * X[idx_i[k]]
// ---------------------------------------------------------------------------
__global__ void scatter_kernel(const float* __restrict__ X,
                               const float* __restrict__ e) {
    int k = blockIdx.x * blockDim.x + threadIdx.x;
    if (k >= EE) return;

    int   ii = g_idx_i[k];
    int   io = g_idx_o[k];
    float ek = e[k];

    float4 xo = reinterpret_cast<const float4*>(X)[io];
    float4 xi = reinterpret_cast<const float4*>(X)[ii];

    float* mi = g_mi + 4 * ii;
    atomicAdd(mi + 0, ek * xo.x);
    atomicAdd(mi + 1, ek * xo.y);
    atomicAdd(mi + 2, ek * xo.z);
    atomicAdd(mi + 3, ek * xo.w);

    float* mo = g_mo + 4 * io;
    atomicAdd(mo + 0, ek * xi.x);
    atomicAdd(mo + 1, ek * xi.y);
    atomicAdd(mo + 2, ek * xi.z);
    atomicAdd(mo + 3, ek * xi.w);
}

// ---------------------------------------------------------------------------
// Fast device math
// ---------------------------------------------------------------------------
__device__ __forceinline__ float fast_tanh(float x) {
    float y;
    asm("tanh.approx.f32 %0, %1;" : "=f"(y) : "f"(x));
    return y;
}

// ---------------------------------------------------------------------------
// Kernel 3: fused MLP  out = sigmoid( tanh([mi,mo,X] @ W1 + b1) @ W2 + b2 )
// 4 threads per node, 25 hidden units each, shfl reduce, tanh.approx (MUFU).
// ---------------------------------------------------------------------------
#define MLP_THREADS 128
#define TPN 4                 // threads per node
#define HPT (HH / TPN)        // 25 hidden units per thread

__global__ __launch_bounds__(MLP_THREADS)
void mlp_kernel(const float* __restrict__ X,
                const float* __restrict__ W1, const float* __restrict__ b1,
                const float* __restrict__ W2, const float* __restrict__ b2,
                float* __restrict__ out) {
    __shared__ float sW1[3 * DD * HH];   // [12][100] row-major
    __shared__ float sb1[HH];
    __shared__ float sW2[HH];

    for (int i = threadIdx.x; i < 3 * DD * HH; i += MLP_THREADS) sW1[i] = W1[i];
    for (int i = threadIdx.x; i < HH; i += MLP_THREADS) {
        sb1[i] = b1[i];
        sW2[i] = W2[i];
    }
    __syncthreads();

    int t = blockIdx.x * MLP_THREADS + threadIdx.x;
    int n = t / TPN;          // node
    int q = t % TPN;          // quarter of hidden units
    if (n >= NN) return;

    float in[3 * DD];
    float4 a = reinterpret_cast<const float4*>(g_mi)[n];
    float4 b = reinterpret_cast<const float4*>(g_mo)[n];
    float4 c = reinterpret_cast<const float4*>(X)[n];
    in[0] = a.x; in[1] = a.y; in[2]  = a.z; in[3]  = a.w;
    in[4] = b.x; in[5] = b.y; in[6]  = b.z; in[7]  = b.w;
    in[8] = c.x; in[9] = c.y; in[10] = c.z; in[11] = c.w;

    float acc = 0.0f;
    const int j0 = q * HPT;
    #pragma unroll 5
    for (int jj = 0; jj < HPT; ++jj) {
        const int j = j0 + jj;
        float s = sb1[j];
        #pragma unroll
        for (int i = 0; i < 3 * DD; ++i)
            s = fmaf(in[i], sW1[i * HH + j], s);
        acc = fmaf(fast_tanh(s), sW2[j], acc);
    }

    // reduce the 4 partial sums within the node's thread quad
    acc += __shfl_xor_sync(0xFFFFFFFFu, acc, 1);
    acc += __shfl_xor_sync(0xFFFFFFFFu, acc, 2);

    if (q == 0) {
        acc += b2[0];
        out[n] = 1.0f / (1.0f + __expf(-acc));
    }
}

// ---------------------------------------------------------------------------
// Launch
// Inputs (metadata order): X, e, Ri, Ro, W1, b1, W2, b2
// ---------------------------------------------------------------------------
extern "C" void kernel_launch(void* const* d_in, const int* in_sizes, int n_in,
                              void* d_out, int out_size) {
    const float* X  = (const float*)d_in[0];
    const float* e  = (const float*)d_in[1];
    const float* Ri = (const float*)d_in[2];
    const float* Ro = (const float*)d_in[3];
    const float* W1 = (const float*)d_in[4];
    const float* b1 = (const float*)d_in[5];
    const float* W2 = (const float*)d_in[6];
    const float* b2 = (const float*)d_in[7];
    float* out = (float*)d_out;

    // 1) persistent one-wave scan over Ri/Ro (HBM-bound) + zero accumulators
    find_idx_kernel<<<SCAN_BLOCKS, SCAN_THREADS>>>(Ri, Ro);

    // 2) per-edge scatter
    scatter_kernel<<<(EE + 255) / 256, 256>>>(X, e);

    // 3) fused MLP (4 threads/node, 256 blocks)
    mlp_kernel<<<(NN * TPN + MLP_THREADS - 1) / MLP_THREADS, MLP_THREADS>>>(
        X, W1, b1, W2, b2, out);
}

// round 6
// speedup vs baseline: 1.0367x; 1.0367x over previous
#include <cuda_runtime.h>
#include <cuda_bf16.h>
#include <math.h>

// Problem constants (fixed by the dataset)
#define NN 8192      // nodes
#define EE 24576     // edges
#define DD 4         // node feature dim
#define HH 100       // hidden units

// ---------------------------------------------------------------------------
// Device scratch (no allocations allowed in kernel_launch)
// ---------------------------------------------------------------------------
__device__ int   g_idx_i[EE];
__device__ int   g_idx_o[EE];
__device__ float g_mi[NN * DD];
__device__ float g_mo[NN * DD];

// ---------------------------------------------------------------------------
// Kernel 1: recover idx_i / idx_o from the dense one-hot incidence matrices,
// and (prologue, subset of blocks) zero the scatter accumulators.
//
// Each column of Ri/Ro [N, E] (row-major) has exactly one 1.0; compute
//   fidx = sum_r r * M[r, c],  found = sum_r M[r, c]
// over a row-chunk. Exactly one (block-row) chunk finds the 1.0 per column,
// so the writer is unique -> plain store, no atomics.
// This kernel is the HBM roofline: 2 * N * E * 4B = 1.61 GB streamed once.
//
// R6: back to the R4 block-per-unit scheme (persistent grid-stride regressed:
// unit-boundary drains beat the wave-tail cost, which HW work-stealing already
// hides). Deepen the load batch 8 -> 16 (64 load regs in flight), 3 blocks/SM.
// ---------------------------------------------------------------------------
#define SCAN_THREADS     256
#define COLS_PER_BLOCK   (SCAN_THREADS * 4)      // 1024
#define ROW_CHUNKS       64
#define ROWS_PER_CHUNK   (NN / ROW_CHUNKS)       // 128
#define BATCH            16

__global__ __launch_bounds__(SCAN_THREADS, 3)
void find_idx_kernel(const float* __restrict__ Ri, const float* __restrict__ Ro) {
    // --- prologue: zero g_mi / g_mo (completes before scatter_kernel via
    //     kernel-boundary ordering).
    if (blockIdx.z == 0 && blockIdx.y < 8) {
        int t = (blockIdx.y * gridDim.x + blockIdx.x) * SCAN_THREADS + threadIdx.x;
        if (t < NN * DD) { g_mi[t] = 0.0f; g_mo[t] = 0.0f; }
    }

    const float* M   = (blockIdx.z == 0) ? Ri : Ro;
    int*         out = (blockIdx.z == 0) ? g_idx_i : g_idx_o;

    const int col = blockIdx.x * COLS_PER_BLOCK + threadIdx.x * 4;
    const int r0  = blockIdx.y * ROWS_PER_CHUNK;

    const float4* p = reinterpret_cast<const float4*>(M + (long)r0 * EE + col);
    const int row_stride4 = EE / 4;  // float4 elements per row

    float fi0 = 0.f, fi1 = 0.f, fi2 = 0.f, fi3 = 0.f;
    float ff0 = 0.f, ff1 = 0.f, ff2 = 0.f, ff3 = 0.f;

    for (int rb = 0; rb < ROWS_PER_CHUNK; rb += BATCH) {
        // front-batch BATCH independent LDG.128s (deep MLP)
        float4 v[BATCH];
        #pragma unroll
        for (int j = 0; j < BATCH; ++j)
            v[j] = __ldcs(p + (long)(rb + j) * row_stride4);   // streaming

        #pragma unroll
        for (int j = 0; j < BATCH; ++j) {
            float fr = (float)(r0 + rb + j);
            fi0 = fmaf(v[j].x, fr, fi0); ff0 += v[j].x;
            fi1 = fmaf(v[j].y, fr, fi1); ff1 += v[j].y;
            fi2 = fmaf(v[j].z, fr, fi2); ff2 += v[j].z;
            fi3 = fmaf(v[j].w, fr, fi3); ff3 += v[j].w;
        }
    }

    if (ff0 != 0.f) out[col + 0] = (int)fi0;
    if (ff1 != 0.f) out[col + 1] = (int)fi1;
    if (ff2 != 0.f) out[col + 2] = (int)fi2;
    if (ff3 != 0.f) out[col + 3] = (int)fi3;
}

// ---------------------------------------------------------------------------
// Kernel 2: per-edge weighted scatter
//   mi[idx_i[k]] += e[k] * X[idx_o[k]]
//   mo[idx_o[k]] += e[k] * X[idx_i[k]]
// ---------------------------------------------------------------------------
__global__ void scatter_kernel(const float* __restrict__ X,
                               const float* __restrict__ e) {
    int k = blockIdx.x * blockDim.x + threadIdx.x;
    if (k >= EE) return;

    int   ii = g_idx_i[k];
    int   io = g_idx_o[k];
    float ek = e[k];

    float4 xo = reinterpret_cast<const float4*>(X)[io];
    float4 xi = reinterpret_cast<const float4*>(X)[ii];

    float* mi = g_mi + 4 * ii;
    atomicAdd(mi + 0, ek * xo.x);
    atomicAdd(mi + 1, ek * xo.y);
    atomicAdd(mi + 2, ek * xo.z);
    atomicAdd(mi + 3, ek * xo.w);

    float* mo = g_mo + 4 * io;
    atomicAdd(mo + 0, ek * xi.x);
    atomicAdd(mo + 1, ek * xi.y);
    atomicAdd(mo + 2, ek * xi.z);
    atomicAdd(mo + 3, ek * xi.w);
}

// ---------------------------------------------------------------------------
// Fast device math
// ---------------------------------------------------------------------------
__device__ __forceinline__ float fast_tanh(float x) {
    float y;
    asm("tanh.approx.f32 %0, %1;" : "=f"(y) : "f"(x));
    return y;
}

// ---------------------------------------------------------------------------
// Kernel 3: fused MLP  out = sigmoid( tanh([mi,mo,X] @ W1 + b1) @ W2 + b2 )
// 4 threads per node, 25 hidden units each, shfl reduce, tanh.approx (MUFU).
// ---------------------------------------------------------------------------
#define MLP_THREADS 128
#define TPN 4                 // threads per node
#define HPT (HH / TPN)        // 25 hidden units per thread

__global__ __launch_bounds__(MLP_THREADS)
void mlp_kernel(const float* __restrict__ X,
                const float* __restrict__ W1, const float* __restrict__ b1,
                const float* __restrict__ W2, const float* __restrict__ b2,
                float* __restrict__ out) {
    __shared__ float sW1[3 * DD * HH];   // [12][100] row-major
    __shared__ float sb1[HH];
    __shared__ float sW2[HH];

    for (int i = threadIdx.x; i < 3 * DD * HH; i += MLP_THREADS) sW1[i] = W1[i];
    for (int i = threadIdx.x; i < HH; i += MLP_THREADS) {
        sb1[i] = b1[i];
        sW2[i] = W2[i];
    }
    __syncthreads();

    int t = blockIdx.x * MLP_THREADS + threadIdx.x;
    int n = t / TPN;          // node
    int q = t % TPN;          // quarter of hidden units
    if (n >= NN) return;

    float in[3 * DD];
    float4 a = reinterpret_cast<const float4*>(g_mi)[n];
    float4 b = reinterpret_cast<const float4*>(g_mo)[n];
    float4 c = reinterpret_cast<const float4*>(X)[n];
    in[0] = a.x; in[1] = a.y; in[2]  = a.z; in[3]  = a.w;
    in[4] = b.x; in[5] = b.y; in[6]  = b.z; in[7]  = b.w;
    in[8] = c.x; in[9] = c.y; in[10] = c.z; in[11] = c.w;

    float acc = 0.0f;
    const int j0 = q * HPT;
    #pragma unroll 5
    for (int jj = 0; jj < HPT; ++jj) {
        const int j = j0 + jj;
        float s = sb1[j];
        #pragma unroll
        for (int i = 0; i < 3 * DD; ++i)
            s = fmaf(in[i], sW1[i * HH + j], s);
        acc = fmaf(fast_tanh(s), sW2[j], acc);
    }

    // reduce the 4 partial sums within the node's thread quad
    acc += __shfl_xor_sync(0xFFFFFFFFu, acc, 1);
    acc += __shfl_xor_sync(0xFFFFFFFFu, acc, 2);

    if (q == 0) {
        acc += b2[0];
        out[n] = 1.0f / (1.0f + __expf(-acc));
    }
}

// ---------------------------------------------------------------------------
// Launch
// Inputs (metadata order): X, e, Ri, Ro, W1, b1, W2, b2
// ---------------------------------------------------------------------------
extern "C" void kernel_launch(void* const* d_in, const int* in_sizes, int n_in,
                              void* d_out, int out_size) {
    const float* X  = (const float*)d_in[0];
    const float* e  = (const float*)d_in[1];
    const float* Ri = (const float*)d_in[2];
    const float* Ro = (const float*)d_in[3];
    const float* W1 = (const float*)d_in[4];
    const float* b1 = (const float*)d_in[5];
    const float* W2 = (const float*)d_in[6];
    const float* b2 = (const float*)d_in[7];
    float* out = (float*)d_out;

    // 1) recover indices from dense one-hot matrices (HBM-bound) + zero accs
    dim3 grid(EE / COLS_PER_BLOCK, ROW_CHUNKS, 2);   // (24, 64, 2) = 3072 blocks
    find_idx_kernel<<<grid, SCAN_THREADS>>>(Ri, Ro);

    // 2) per-edge scatter
    scatter_kernel<<<(EE + 255) / 256, 256>>>(X, e);

    // 3) fused MLP (4 threads/node, 256 blocks)
    mlp_kernel<<<(NN * TPN + MLP_THREADS - 1) / MLP_THREADS, MLP_THREADS>>>(
        X, W1, b1, W2, b2, out);
}